// round 9
// baseline (speedup 1.0000x reference)
#include <cuda_runtime.h>

// Problem constants (match reference)
#define NN 50000
#define EE 800000
#define FF 128
#define HH 128
#define CC 10
#define GG 512

// ---------------- device scratch (no allocations allowed) ----------------
__device__ int   g_ei64;            // 1 if edge_index is int64, else int32
__device__ int   g_b64;             // 1 if batch is int64
__device__ int   g_deg[NN];
__device__ int   g_rowptr[NN + 1];
__device__ int   g_cursor[NN];
__device__ int   g_csr[EE];         // src node per CSR slot (grouped by dst)
__device__ float g_dinv[NN];
__device__ float g_bufA[NN * HH];
__device__ float g_bufB[NN * HH];

// ---------------- helpers ----------------
__device__ __forceinline__ int ld_idx(const void* p, long long i, int is64) {
    if (is64) return (int)((const long long*)p)[i];
    return ((const int*)p)[i];
}

// Detect int32 vs int64 index buffers. For int64 little-endian values < 2^31,
// every odd 32-bit word is zero. Sample odd words spread across the region.
__global__ void k_detect(const int* ei, const int* batch) {
    if (blockIdx.x == 0 && threadIdx.x == 0) {
        int nz = 0;
        for (int k = 0; k < 128; k++) {
            long long j = 2LL * k * (EE / 256) + 1;   // odd word in [0, EE)
            nz += (ei[j] != 0);
        }
        g_ei64 = (nz == 0) ? 1 : 0;
        nz = 0;
        for (int k = 0; k < 128; k++) {
            long long j = 2LL * k * (NN / 256) + 1;   // odd word in [0, NN)
            nz += (batch[j] != 0);
        }
        g_b64 = (nz == 0) ? 1 : 0;
    }
}

__global__ void k_zero() {
    int i = blockIdx.x * blockDim.x + threadIdx.x;
    int stride = gridDim.x * blockDim.x;
    for (; i < NN; i += stride) { g_deg[i] = 0; g_cursor[i] = 0; }
}

__global__ void k_count(const void* ei) {
    int is64 = g_ei64;
    int i = blockIdx.x * blockDim.x + threadIdx.x;
    int stride = gridDim.x * blockDim.x;
    for (; i < EE; i += stride) {
        int d = ld_idx(ei, (long long)EE + i, is64);
        atomicAdd(&g_deg[d], 1);
    }
}

__global__ void k_dinv() {
    int i = blockIdx.x * blockDim.x + threadIdx.x;
    int stride = gridDim.x * blockDim.x;
    for (; i < NN; i += stride)
        g_dinv[i] = rsqrtf((float)g_deg[i] + 1.0f);   // +1 for self-loop
}

// exclusive prefix sum of g_deg -> g_rowptr, single block of 1024 threads
__global__ void k_scan() {
    __shared__ int sums[1024];
    const int CHUNK = (NN + 1023) / 1024;             // 49
    int t = threadIdx.x;
    int lo = t * CHUNK;
    int hi = lo + CHUNK; if (hi > NN) hi = NN;
    int s = 0;
    if (lo < NN) for (int i = lo; i < hi; i++) s += g_deg[i];
    sums[t] = s;
    __syncthreads();
    for (int off = 1; off < 1024; off <<= 1) {
        int v = (t >= off) ? sums[t - off] : 0;
        __syncthreads();
        sums[t] += v;
        __syncthreads();
    }
    int run = (t == 0) ? 0 : sums[t - 1];
    if (lo < NN) {
        for (int i = lo; i < hi; i++) { g_rowptr[i] = run; run += g_deg[i]; }
        if (hi == NN) g_rowptr[NN] = run;
    }
}

__global__ void k_fill(const void* ei) {
    int is64 = g_ei64;
    int i = blockIdx.x * blockDim.x + threadIdx.x;
    int stride = gridDim.x * blockDim.x;
    for (; i < EE; i += stride) {
        int s = ld_idx(ei, (long long)i, is64);
        int d = ld_idx(ei, (long long)EE + i, is64);
        int pos = atomicAdd(&g_cursor[d], 1);
        g_csr[g_rowptr[d] + pos] = s;
    }
}

// ---------------- GEMM: Out[N,128] = A[N,128] @ W[128,128] ----------------
// Tile: 64 rows x 128 cols, BK=32, 256 threads, micro-tile 4x8 per thread.
#define BM 64
#define BK 32
__device__ __forceinline__ void gemm_body(const float* __restrict__ A,
                                          const float* __restrict__ W,
                                          float* __restrict__ Out) {
    __shared__ float As[BM][BK + 4];   // +4 pad: keeps float4 STS aligned, kills bank conflicts
    __shared__ float Ws[BK][HH];
    int t = threadIdx.x;
    int block_row = blockIdx.x * BM;
    int tr = t >> 4;       // 0..15 -> rows tr*4 .. tr*4+3
    int tc = t & 15;       // 0..15 -> cols tc*8 .. tc*8+7
    float acc[4][8];
#pragma unroll
    for (int i = 0; i < 4; i++)
#pragma unroll
        for (int j = 0; j < 8; j++) acc[i][j] = 0.f;

    for (int k0 = 0; k0 < FF; k0 += BK) {
        // load A tile: 64x32 floats = 2 float4 per thread
#pragma unroll
        for (int i = 0; i < 2; i++) {
            int f = (t * 2 + i) * 4;
            int r = f >> 5, c = f & 31;
            int grow = block_row + r;
            float4 v = make_float4(0.f, 0.f, 0.f, 0.f);
            if (grow < NN) v = *(const float4*)&A[(long long)grow * FF + k0 + c];
            *(float4*)&As[r][c] = v;
        }
        // load W tile: 32x128 floats = 4 float4 per thread
#pragma unroll
        for (int i = 0; i < 4; i++) {
            int f = (t * 4 + i) * 4;
            int r = f >> 7, c = f & 127;
            *(float4*)&Ws[r][c] = *(const float4*)&W[(k0 + r) * HH + c];
        }
        __syncthreads();
#pragma unroll
        for (int kk = 0; kk < BK; kk++) {
            float a[4], b[8];
#pragma unroll
            for (int i = 0; i < 4; i++) a[i] = As[tr * 4 + i][kk];
#pragma unroll
            for (int j = 0; j < 8; j++) b[j] = Ws[kk][tc * 8 + j];
#pragma unroll
            for (int i = 0; i < 4; i++)
#pragma unroll
                for (int j = 0; j < 8; j++) acc[i][j] = fmaf(a[i], b[j], acc[i][j]);
        }
        __syncthreads();
    }
#pragma unroll
    for (int i = 0; i < 4; i++) {
        int grow = block_row + tr * 4 + i;
        if (grow < NN) {
            float4 v0 = make_float4(acc[i][0], acc[i][1], acc[i][2], acc[i][3]);
            float4 v1 = make_float4(acc[i][4], acc[i][5], acc[i][6], acc[i][7]);
            *(float4*)&Out[(long long)grow * HH + tc * 8]     = v0;
            *(float4*)&Out[(long long)grow * HH + tc * 8 + 4] = v1;
        }
    }
}

__global__ void k_gemm_x(const float* __restrict__ x, const float* __restrict__ W) {
    gemm_body(x, W, g_bufA);               // layer 1: x @ W1 -> bufA
}
__global__ void k_gemm_h(const float* __restrict__ W) {
    gemm_body(g_bufB, W, g_bufA);          // layer 2: h1 @ W2 -> bufA
}

// -------- aggregate: out[i] = relu(dinv[i]*(sum_{s in N(i)} h[s]*dinv[s] + h[i]*dinv[i]) + b)
// one warp per node, each lane owns one float4 (4 features)
__device__ __forceinline__ void agg_body(const float* __restrict__ h,
                                         const float* __restrict__ bias,
                                         float* __restrict__ out) {
    int gw = (blockIdx.x * blockDim.x + threadIdx.x) >> 5;
    int lane = threadIdx.x & 31;
    if (gw >= NN) return;
    float di = g_dinv[gw];
    int lo = g_rowptr[gw], hi = g_rowptr[gw + 1];
    const float4* hp = (const float4*)h;
    float4 acc = hp[(long long)gw * 32 + lane];     // self term: h[i]*dinv[i]
    acc.x *= di; acc.y *= di; acc.z *= di; acc.w *= di;

    int e = lo;
    int s_next = (e < hi) ? g_csr[e] : 0;
    while (e < hi) {
        int s = s_next;
        e++;
        if (e < hi) s_next = g_csr[e];              // software prefetch of next index
        float w = g_dinv[s];
        float4 v = hp[(long long)s * 32 + lane];
        acc.x = fmaf(v.x, w, acc.x);
        acc.y = fmaf(v.y, w, acc.y);
        acc.z = fmaf(v.z, w, acc.z);
        acc.w = fmaf(v.w, w, acc.w);
    }
    float4 b4 = ((const float4*)bias)[lane];
    float4 o;
    o.x = fmaxf(fmaf(acc.x, di, b4.x), 0.f);
    o.y = fmaxf(fmaf(acc.y, di, b4.y), 0.f);
    o.z = fmaxf(fmaf(acc.z, di, b4.z), 0.f);
    o.w = fmaxf(fmaf(acc.w, di, b4.w), 0.f);
    ((float4*)out)[(long long)gw * 32 + lane] = o;
}

__global__ void k_agg(const float* __restrict__ bias) {
    agg_body(g_bufA, bias, g_bufB);        // both layers: bufA -> bufB
}

// -------- pool + classifier: one block per graph (batch is sorted) --------
__device__ __forceinline__ int lb_batch(const void* b, int is64, int val) {
    int lo = 0, hi = NN;
    while (lo < hi) {
        int m = (lo + hi) >> 1;
        if (ld_idx(b, m, is64) < val) lo = m + 1; else hi = m;
    }
    return lo;
}

__global__ void k_pool(const void* __restrict__ batch,
                       const float* __restrict__ Wl,
                       const float* __restrict__ bl,
                       float* __restrict__ out) {
    int g = blockIdx.x, t = threadIdx.x;   // 128 threads
    __shared__ int s_lo, s_hi;
    if (t == 0) {
        int is64 = g_b64;
        s_lo = lb_batch(batch, is64, g);
        s_hi = lb_batch(batch, is64, g + 1);
    }
    __syncthreads();
    int lo = s_lo, hi = s_hi;
    float sum = 0.f;
    for (int i = lo; i < hi; i++) sum += g_bufB[(long long)i * HH + t];
    float cnt = (hi > lo) ? (float)(hi - lo) : 1.0f;
    __shared__ float sp[HH];
    sp[t] = sum / cnt;
    __syncthreads();
    if (t < CC) {
        float a = bl[t];
#pragma unroll 8
        for (int k = 0; k < HH; k++) a = fmaf(sp[k], Wl[k * CC + t], a);
        out[g * CC + t] = a;
    }
}

// ---------------- launch ----------------
extern "C" void kernel_launch(void* const* d_in, const int* in_sizes, int n_in,
                              void* d_out, int out_size) {
    const float* x     = (const float*)d_in[0];
    const void*  ei    = d_in[1];
    const void*  batch = d_in[2];
    const float* W1    = (const float*)d_in[3];
    const float* b1    = (const float*)d_in[4];
    const float* W2    = (const float*)d_in[5];
    const float* b2    = (const float*)d_in[6];
    const float* Wl    = (const float*)d_in[7];
    const float* bl    = (const float*)d_in[8];
    float* out         = (float*)d_out;

    // graph structure (recomputed every call; deterministic work)
    k_detect<<<1, 32>>>((const int*)ei, (const int*)batch);
    k_zero<<<96, 256>>>();
    k_count<<<512, 256>>>(ei);
    k_dinv<<<96, 256>>>();
    k_scan<<<1, 1024>>>();
    k_fill<<<512, 256>>>(ei);

    const int gemm_grid = (NN + BM - 1) / BM;              // 782
    const int agg_grid  = (NN * 32 + 255) / 256;           // 6250

    // layer 1
    k_gemm_x<<<gemm_grid, 256>>>(x, W1);                   // bufA = x @ W1
    k_agg<<<agg_grid, 256>>>(b1);                          // bufB = relu(prop(bufA) + b1)
    // layer 2
    k_gemm_h<<<gemm_grid, 256>>>(W2);                      // bufA = bufB @ W2
    k_agg<<<agg_grid, 256>>>(b2);                          // bufB = relu(prop(bufA) + b2)
    // pool + classifier
    k_pool<<<GG, HH>>>(batch, Wl, bl, out);
}